// round 15
// baseline (speedup 1.0000x reference)
#include <cuda_runtime.h>
#include <cuda_fp16.h>
#include <math.h>
#include <stdint.h>

#define BATCH 512
#define NTOT  65536
typedef unsigned long long u64;
typedef unsigned int u32;

// ---------------- scratch (device globals) ----------------
__device__ __half g_Gf[(size_t)NTOT * 1536];
__device__ __half g_Wf[512 * 640 + 512 * 1536 + 256 * 1536];
__device__ float g_x1[(size_t)512 * NTOT];   // unshifted, channel-major [h][n]
__device__ float g_x2[(size_t)512 * NTOT];
__device__ float g_emb[(size_t)256 * NTOT];
__device__ float g_stats[4 * BATCH];

__device__ __forceinline__ void cpa16(u32 s, const void* g) {
    asm volatile("cp.async.cg.shared.global [%0], [%1], 16;" :: "r"(s), "l"(g));
}
#define CPA_COMMIT() asm volatile("cp.async.commit_group;")
template<int N> __device__ __forceinline__ void cpa_wait() {
    asm volatile("cp.async.wait_group %0;" :: "n"(N));
}
__device__ __forceinline__ void ldsm4(u32* r, u32 addr) {
    asm volatile("ldmatrix.sync.aligned.m8n8.x4.shared.b16 {%0,%1,%2,%3}, [%4];"
        : "=r"(r[0]), "=r"(r[1]), "=r"(r[2]), "=r"(r[3]) : "r"(addr));
}
__device__ __forceinline__ void mma16816(float* c, const u32* a, const u32* b) {
    asm volatile("mma.sync.aligned.m16n8k16.row.col.f32.f16.f16.f32 "
        "{%0,%1,%2,%3}, {%4,%5,%6,%7}, {%8,%9}, {%0,%1,%2,%3};"
        : "+f"(c[0]), "+f"(c[1]), "+f"(c[2]), "+f"(c[3])
        : "r"(a[0]), "r"(a[1]), "r"(a[2]), "r"(a[3]), "r"(b[0]), "r"(b[1]));
}

// ---------------- W convert + K-pad: wf[h][KPAD] fp16 ----------------
__global__ void wsplit_kernel(const float* __restrict__ w, __half* __restrict__ wf,
                              int K, int KPAD, int total)
{
    int e = blockIdx.x * 256 + threadIdx.x;
    if (e >= total) return;
    int h = e / KPAD, k = e - h * KPAD;
    float v = (k < K) ? w[(size_t)h * K + k] : 0.f;
    wf[e] = __float2half_rn(v);
}

// ---------------- gather v7: direct idx_s indexing, no select chains ----------
// G[b*128+j][kbase+k] = T(x at idx). Coalesced u32 stores (lane -> kp).
// MODE 0: in = trees [B][CIN][128], direct idx.
// MODE 1: in = x [CIN][NTOT] unshifted; idx==0 -> sentinel slot 128 (= relu(-mean*inv)),
//         else normed x[idx-1].
#define XPAD 132
template<int CCH, int KPAD, int MODE>
__global__ __launch_bounds__(256)
void gather_kernel(const float* __restrict__ in, const int* __restrict__ idxg,
                   const float* __restrict__ stats_in,
                   __half* __restrict__ Gf, int CIN)
{
    const int b = blockIdx.y, blk = blockIdx.x, tid = threadIdx.x;
    const int c0 = blk * CCH;
    const int kbase = 3 * c0;
    const int klen = (KPAD - kbase < 3 * CCH) ? (KPAD - kbase) : (3 * CCH);
    __shared__ int   idx_s[384];
    __shared__ float x_s[CCH * XPAD];

    float mean = 0.f, inv = 1.f, v0 = 0.f;
    if (MODE == 1) {
        float s  = stats_in[2 * b];
        float s2 = stats_in[2 * b + 1];
        const float N = 65536.f;
        float m   = s / N;
        float var = (s2 - s * s / N) * (1.f / 65535.f);
        mean = m;
        inv  = 1.f / (sqrtf(fmaxf(var, 0.f)) + 1e-5f);
        v0   = fmaxf(-mean * inv, 0.f);
    }
    for (int i = tid; i < 384; i += 256) {
        int v = (i < 381) ? idxg[b * 381 + i] : 0;
        idx_s[i] = (MODE == 1) ? (v ? v - 1 : 128) : v;
    }
    for (int q = tid; q < CCH * 32; q += 256) {
        int cl = q >> 5, vq = q & 31;
        float4 v = make_float4(0.f, 0.f, 0.f, 0.f);
        if (c0 + cl < CIN) {
            const float* src = (MODE == 0)
                ? in + ((size_t)b * CIN + c0 + cl) * 128 + vq * 4
                : in + (size_t)(c0 + cl) * NTOT + b * 128 + vq * 4;
            v = *(const float4*)src;
            if (MODE == 1) {
                v.x = fmaxf((v.x - mean) * inv, 0.f);
                v.y = fmaxf((v.y - mean) * inv, 0.f);
                v.z = fmaxf((v.z - mean) * inv, 0.f);
                v.w = fmaxf((v.w - mean) * inv, 0.f);
            }
        }
        *(float4*)&x_s[cl * XPAD + vq * 4] = v;
    }
    if (MODE == 1) {
        for (int cl = tid; cl < CCH; cl += 256) x_s[cl * XPAD + 128] = v0;
    }
    __syncthreads();

    const int wid = tid >> 5, lane = tid & 31;

    // per-lane invariant tap descriptors: x-row base pointer + tap slot (0/1/2)
    const int NIT = (3 * CCH + 63) / 64;
    const float* xA[3];
    const float* xB[3];
    int rAi[3], rBi[3];
    int nit = 0;
    #pragma unroll
    for (int it = 0; it < NIT && it < 3; it++) {
        int kp = lane + 32 * it;
        if (2 * kp < klen) {
            int e0 = 2 * kp, e1 = e0 + 1;
            int cl0 = e0 / 3, cl1 = e1 / 3;
            xA[it] = x_s + cl0 * XPAD; rAi[it] = e0 - 3 * cl0;
            xB[it] = x_s + cl1 * XPAD; rBi[it] = e1 - 3 * cl1;
            nit = it + 1;
        }
    }

    for (int j = wid; j < 128; j += 8) {
        const size_t wbase = ((size_t)(b * 128 + j) * KPAD + kbase) >> 1;
        if (j == 127) {
            for (int it = 0; it < nit; it++)
                ((u32*)Gf)[wbase + lane + 32 * it] = 0u;
            continue;
        }
        const int jb3 = 3 * j;
        #pragma unroll
        for (int it = 0; it < 3; it++) {
            if (it >= nit) break;
            int iA = idx_s[jb3 + rAi[it]];     // broadcast-ish LDS (3 addrs/warp)
            int iB = idx_s[jb3 + rBi[it]];
            float va = xA[it][iA];
            float vb = xB[it][iB];
            __half2 h2 = __floats2half2_rn(va, vb);
            ((u32*)Gf)[wbase + lane + 32 * it] = *(u32*)&h2;
        }
    }
}

// ---------------- warp-MMA fp16 GEMM (k-tile 64, single sync per tile) -------
// D[h0..h0+128)[n0..n0+128) = sum_k Wf[h][k]*Gf[n][k]
// 256 thr = 8 warps (2m x 4n); warp tile 64m x 32n; k-tile 64,
// double-buffered cp.async: wait -> sync -> stage(c+1) -> mma.
#define HPITCH 144
#define HPLANE (128 * HPITCH)     // 18432
#define HSTAGE (2 * HPLANE)       // 36864: A plane + B plane
#define HSMEM  (2 * HSTAGE)       // 73728

template<int KPAD, int STATS>
__global__ __launch_bounds__(256)
void hmma_gemm_kernel(const __half* __restrict__ Gf, const __half* __restrict__ Wf,
                      const float* __restrict__ bias, float* __restrict__ stats_out,
                      float* __restrict__ out)
{
    extern __shared__ char dsm[];
    __shared__ float bias_s[128];
    __shared__ float rsum[8], rsq[8];
    const int tid = threadIdx.x, wid = tid >> 5, lid = tid & 31;
    const int wm = wid & 1, wn = wid >> 1;
    const int h0 = blockIdx.x * 128;
    const int n0 = blockIdx.y * 128;       // one batch per CTA
    const u32 sbase = (u32)__cvta_generic_to_shared(dsm);

    if (tid < 128) bias_s[tid] = bias[h0 + tid];

    const __half* pl[2] = { Wf + (size_t)h0 * KPAD, Gf + (size_t)n0 * KPAD };

    float acc[4][4][4];
    #pragma unroll
    for (int mi = 0; mi < 4; mi++)
        #pragma unroll
        for (int ni = 0; ni < 4; ni++)
            #pragma unroll
            for (int r = 0; r < 4; r++) acc[mi][ni][r] = 0.f;

    auto stage = [&](int c, int st) {
        int k0 = c * 64;
        u32 sb = sbase + st * HSTAGE;
        #pragma unroll
        for (int i = 0; i < 8; i++) {
            int q = tid + i * 256;                  // 0..2047
            int plane = q >> 10, rem = q & 1023, row = rem >> 3, kc = rem & 7;
            u32 dst = sb + plane * HPLANE + row * HPITCH + kc * 16;
            cpa16(dst, pl[plane] + (size_t)row * KPAD + k0 + kc * 8);
        }
        CPA_COMMIT();
    };

    constexpr int NC = KPAD / 64;
    stage(0, 0);
    for (int c = 0; c < NC; c++) {
        int st = c & 1;
        cpa_wait<0>();
        __syncthreads();
        if (c + 1 < NC) stage(c + 1, st ^ 1);
        u32 sw0 = sbase + st * HSTAGE;
        #pragma unroll
        for (int s2 = 0; s2 < 4; s2++) {
            u32 ah[4][4], bh2[4][2];
            int gAr = ((lid >> 3) & 1) * 8 + (lid & 7);
            int gAb = (lid >> 4) * 16 + s2 * 32;
            #pragma unroll
            for (int mi = 0; mi < 4; mi++) {
                int row = wm * 64 + mi * 16 + gAr;
                ldsm4(ah[mi], sw0 + row * HPITCH + gAb);
            }
            int gBr = (lid >> 4) * 8 + (lid & 7);
            int gBb = ((lid >> 3) & 1) * 16 + s2 * 32;
            #pragma unroll
            for (int t = 0; t < 2; t++) {
                int row = wn * 32 + t * 16 + gBr;
                u32 r4[4];
                ldsm4(r4, sw0 + HPLANE + row * HPITCH + gBb);
                bh2[2 * t][0] = r4[0]; bh2[2 * t][1] = r4[1];
                bh2[2 * t + 1][0] = r4[2]; bh2[2 * t + 1][1] = r4[3];
            }
            #pragma unroll
            for (int mi = 0; mi < 4; mi++)
                #pragma unroll
                for (int ni = 0; ni < 4; ni++) mma16816(acc[mi][ni], ah[mi], bh2[ni]);
        }
    }

    // epilogue: bias + col127->0 + stats + float2 stores
    float lsum = 0.f, lsq = 0.f;
    #pragma unroll
    for (int mi = 0; mi < 4; mi++) {
        #pragma unroll
        for (int ni = 0; ni < 4; ni++) {
            float* cf = acc[mi][ni];
            int hb = h0 + wm * 64 + mi * 16 + (lid >> 2);
            int nb = n0 + wn * 32 + ni * 8 + (lid & 3) * 2;
            int j0 = nb & 127;
            #pragma unroll
            for (int half = 0; half < 2; half++) {
                int h = hb + half * 8;
                float bb = bias_s[h - h0];
                float v0 = cf[half * 2 + 0] + bb;
                float v1 = (j0 == 126) ? 0.f : cf[half * 2 + 1] + bb;
                if (STATS) { lsum += v0 + v1; lsq += v0 * v0 + v1 * v1; }
                float2 stv = make_float2(v0, v1);
                *(float2*)(out + (size_t)h * NTOT + nb) = stv;
            }
        }
    }
    if (STATS) {
        #pragma unroll
        for (int o = 16; o > 0; o >>= 1) {
            lsum += __shfl_xor_sync(0xffffffffu, lsum, o);
            lsq  += __shfl_xor_sync(0xffffffffu, lsq,  o);
        }
        if (lid == 0) { rsum[wid] = lsum; rsq[wid] = lsq; }
        __syncthreads();
        if (tid == 0) {
            float a = 0.f, c2 = 0.f;
            #pragma unroll
            for (int i = 0; i < 8; i++) { a += rsum[i]; c2 += rsq[i]; }
            atomicAdd(&stats_out[2 * blockIdx.y],     a);
            atomicAdd(&stats_out[2 * blockIdx.y + 1], c2);
        }
    }
}

// ---------------- fp32x2 helpers (gate kernel) ----------------
__device__ __forceinline__ u64 fma2(u64 a, u64 b, u64 c) {
    u64 d;
    asm("fma.rn.f32x2 %0, %1, %2, %3;" : "=l"(d) : "l"(a), "l"(b), "l"(c));
    return d;
}
__device__ __forceinline__ u64 rep2(float x) {
    u64 d;
    asm("mov.b64 %0, {%1, %1};" : "=l"(d) : "f"(x));
    return d;
}
__device__ __forceinline__ float2 unpk(u64 a) {
    float2 r;
    asm("mov.b64 {%0, %1}, %2;" : "=f"(r.x), "=f"(r.y) : "l"(a));
    return r;
}

// ---------------- gate + softmax + pool + combined (emb [f][NTOT] unshifted) --
#define GATE_SMEM_FLOATS (256 * 132 + 32 * 130 + 16 * 128 + 128 + 8)
__global__ __launch_bounds__(512, 1)
void gate_kernel(const float* __restrict__ emb, const float* __restrict__ gw1,
                 const float* __restrict__ gb1, const float* __restrict__ gw2,
                 const float* __restrict__ gb2, float* __restrict__ comb)
{
    extern __shared__ float sm[];
    float* et     = sm;
    float* wc     = et + 256 * 132;
    float* red    = wc + 32 * 130;
    float* logits = red + 16 * 128;
    float* rtmp   = logits + 128;

    int b = blockIdx.x, tid = threadIdx.x;
    int tx = tid & 31, ty = tid >> 5;
    const float* eb = emb + (size_t)b * 128;

    for (int q = tid; q < 256 * 32; q += 512) {
        int f = q >> 5, nq = q & 31;
        float4 v = *(const float4*)(eb + (size_t)f * NTOT + nq * 4);
        float* d = &et[f * 132 + nq * 4 + 1];
        d[0] = v.x; d[1] = v.y; d[2] = v.z; d[3] = v.w;
        if (nq == 0) et[f * 132] = 0.f;
    }

    u64 acc[4][4];
    const u64* gb1p = (const u64*)gb1;
    #pragma unroll
    for (int p = 0; p < 4; p++) {
        u64 bp = gb1p[ty * 4 + p];
        #pragma unroll
        for (int u = 0; u < 4; u++) acc[p][u] = bp;
    }
    __syncthreads();

    for (int fc = 0; fc < 256; fc += 32) {
        for (int q = tid; q < 1024; q += 512) {
            int h = q >> 3, flq = q & 7;
            float4 v = *(const float4*)(gw1 + h * 256 + fc + flq * 4);
            wc[(flq * 4 + 0) * 130 + h] = v.x;
            wc[(flq * 4 + 1) * 130 + h] = v.y;
            wc[(flq * 4 + 2) * 130 + h] = v.z;
            wc[(flq * 4 + 3) * 130 + h] = v.w;
        }
        __syncthreads();
        #pragma unroll 4
        for (int fl = 0; fl < 32; fl++) {
            const u64* wp = (const u64*)&wc[fl * 130 + ty * 8];
            u64 wv[4] = {wp[0], wp[1], wp[2], wp[3]};
            float4 g4 = *(const float4*)&et[(fc + fl) * 132 + tx * 4];
            u64 gp0 = rep2(g4.x), gp1 = rep2(g4.y), gp2 = rep2(g4.z), gp3 = rep2(g4.w);
            #pragma unroll
            for (int p = 0; p < 4; p++) {
                acc[p][0] = fma2(wv[p], gp0, acc[p][0]);
                acc[p][1] = fma2(wv[p], gp1, acc[p][1]);
                acc[p][2] = fma2(wv[p], gp2, acc[p][2]);
                acc[p][3] = fma2(wv[p], gp3, acc[p][3]);
            }
        }
        __syncthreads();
    }

    const u64* gw2p = (const u64*)gw2;
    float part[4] = {0.f, 0.f, 0.f, 0.f};
    #pragma unroll
    for (int p = 0; p < 4; p++) {
        float2 wv = unpk(gw2p[ty * 4 + p]);
        #pragma unroll
        for (int u = 0; u < 4; u++) {
            float2 v = unpk(acc[p][u]);
            part[u] += fmaxf(v.x, 0.f) * wv.x + fmaxf(v.y, 0.f) * wv.y;
        }
    }
    #pragma unroll
    for (int u = 0; u < 4; u++) red[ty * 128 + tx * 4 + u] = part[u];
    __syncthreads();

    if (tid < 128) {
        float s = gb2[0];
        #pragma unroll
        for (int t = 0; t < 16; t++) s += red[t * 128 + tid];
        logits[tid] = s;
    }
    __syncthreads();
    if (tid < 128) {
        float v = logits[tid];
        for (int o = 16; o > 0; o >>= 1) v = fmaxf(v, __shfl_xor_sync(0xffffffffu, v, o));
        if ((tid & 31) == 0) rtmp[tid >> 5] = v;
    }
    __syncthreads();
    float gmax = fmaxf(fmaxf(rtmp[0], rtmp[1]), fmaxf(rtmp[2], rtmp[3]));
    if (tid < 128) logits[tid] = expf(logits[tid] - gmax);
    __syncthreads();
    if (tid < 128) {
        float v = logits[tid];
        for (int o = 16; o > 0; o >>= 1) v += __shfl_xor_sync(0xffffffffu, v, o);
        if ((tid & 31) == 0) rtmp[4 + (tid >> 5)] = v;
    }
    __syncthreads();
    float rinv = 1.f / (rtmp[4] + rtmp[5] + rtmp[6] + rtmp[7]);
    if (tid < 128) logits[tid] *= rinv;
    __syncthreads();

    if (tid < 256) {
        int f = tid;
        float pv = 0.f;
        #pragma unroll 8
        for (int n = 0; n < 128; n++) pv += logits[n] * et[f * 132 + n];
        comb[(size_t)b * 512 + f]       = et[f * 132 + 1];
        comb[(size_t)b * 512 + 256 + f] = pv;
    }
}

// ---------------- tiny MLP head ----------------
__global__ __launch_bounds__(128)
void head_kernel(const float* __restrict__ comb,
                 const float* __restrict__ rw1, const float* __restrict__ rb1,
                 const float* __restrict__ rw2, const float* __restrict__ rb2,
                 const float* __restrict__ rw3, const float* __restrict__ rb3,
                 float* __restrict__ outv)
{
    __shared__ float cs[512];
    __shared__ float wcs[128][33];
    __shared__ float h1[128];
    __shared__ float h2[64];
    int b = blockIdx.x, tid = threadIdx.x;

    for (int i = tid; i < 512; i += 128) cs[i] = comb[(size_t)b * 512 + i];

    float a = rb1[tid];
    for (int i0 = 0; i0 < 512; i0 += 32) {
        for (int e = tid; e < 128 * 32; e += 128) {
            int h = e >> 5, il = e & 31;
            wcs[h][il] = rw1[h * 512 + i0 + il];
        }
        __syncthreads();
        #pragma unroll
        for (int il = 0; il < 32; il++) a += cs[i0 + il] * wcs[tid][il];
        __syncthreads();
    }
    h1[tid] = fmaxf(a, 0.f);
    __syncthreads();

    float a2 = (tid < 64) ? rb2[tid] : 0.f;
    for (int i0 = 0; i0 < 128; i0 += 32) {
        for (int e = tid; e < 64 * 32; e += 128) {
            int h = e >> 5, il = e & 31;
            wcs[h][il] = rw2[h * 128 + i0 + il];
        }
        __syncthreads();
        if (tid < 64) {
            #pragma unroll
            for (int il = 0; il < 32; il++) a2 += h1[i0 + il] * wcs[tid][il];
        }
        __syncthreads();
    }
    if (tid < 64) h2[tid] = fmaxf(a2, 0.f);
    __syncthreads();

    if (tid < 64) {
        float p = h2[tid] * rw3[tid];
        for (int o = 16; o > 0; o >>= 1) p += __shfl_xor_sync(0xffffffffu, p, o);
        if ((tid & 31) == 0) h1[64 + (tid >> 5)] = p;
    }
    __syncthreads();
    if (tid == 0) outv[b] = h1[64] + h1[65] + rb3[0];
}

// ---------------- launch ----------------
extern "C" void kernel_launch(void* const* d_in, const int* in_sizes, int n_in,
                              void* d_out, int out_size)
{
    const float* trees = (const float*)d_in[0];
    const int*   idx   = (const int*)  d_in[1];
    const float* w1    = (const float*)d_in[2];
    const float* b1    = (const float*)d_in[3];
    const float* w2    = (const float*)d_in[4];
    const float* b2    = (const float*)d_in[5];
    const float* w3    = (const float*)d_in[6];
    const float* b3    = (const float*)d_in[7];
    const float* gw1   = (const float*)d_in[8];
    const float* gb1   = (const float*)d_in[9];
    const float* gw2   = (const float*)d_in[10];
    const float* gb2   = (const float*)d_in[11];
    const float* rw1   = (const float*)d_in[12];
    const float* rb1   = (const float*)d_in[13];
    const float* rw2   = (const float*)d_in[14];
    const float* rb2   = (const float*)d_in[15];
    const float* rw3   = (const float*)d_in[16];
    const float* rb3   = (const float*)d_in[17];

    float* out  = (float*)d_out;
    float* comb = out + 512;

    float *x1, *x2, *embp, *st;
    __half *Gf, *Wf;
    cudaGetSymbolAddress((void**)&x1,   g_x1);
    cudaGetSymbolAddress((void**)&x2,   g_x2);
    cudaGetSymbolAddress((void**)&embp, g_emb);
    cudaGetSymbolAddress((void**)&Gf,   g_Gf);
    cudaGetSymbolAddress((void**)&Wf,   g_Wf);
    cudaGetSymbolAddress((void**)&st,   g_stats);
    __half* Wf1 = Wf;
    __half* Wf2 = Wf + 512 * 640;
    __half* Wf3 = Wf2 + 512 * 1536;
    float* st1 = st;
    float* st2 = st + 2 * BATCH;

    cudaFuncSetAttribute(hmma_gemm_kernel<640, 1>,  cudaFuncAttributeMaxDynamicSharedMemorySize, HSMEM);
    cudaFuncSetAttribute(hmma_gemm_kernel<1536, 1>, cudaFuncAttributeMaxDynamicSharedMemorySize, HSMEM);
    cudaFuncSetAttribute(hmma_gemm_kernel<1536, 0>, cudaFuncAttributeMaxDynamicSharedMemorySize, HSMEM);
    size_t gate_smem = (size_t)GATE_SMEM_FLOATS * sizeof(float);
    cudaFuncSetAttribute(gate_kernel, cudaFuncAttributeMaxDynamicSharedMemorySize, (int)gate_smem);

    cudaMemsetAsync(st, 0, 4 * BATCH * sizeof(float));

    wsplit_kernel<<<(512 * 640  + 255) / 256, 256>>>(w1, Wf1, 600,  640,  512 * 640);
    wsplit_kernel<<<(512 * 1536 + 255) / 256, 256>>>(w2, Wf2, 1536, 1536, 512 * 1536);
    wsplit_kernel<<<(256 * 1536 + 255) / 256, 256>>>(w3, Wf3, 1536, 1536, 256 * 1536);

    // layer 1
    gather_kernel<40, 640, 0><<<dim3(6, BATCH), 256>>>(trees, idx, nullptr, Gf, 200);
    hmma_gemm_kernel<640, 1><<<dim3(4, BATCH), 256, HSMEM>>>(Gf, Wf1, b1, st1, x1);
    // layer 2
    gather_kernel<64, 1536, 1><<<dim3(8, BATCH), 256>>>(x1, idx, st1, Gf, 512);
    hmma_gemm_kernel<1536, 1><<<dim3(4, BATCH), 256, HSMEM>>>(Gf, Wf2, b2, st2, x2);
    // layer 3
    gather_kernel<64, 1536, 1><<<dim3(8, BATCH), 256>>>(x2, idx, st2, Gf, 512);
    hmma_gemm_kernel<1536, 0><<<dim3(2, BATCH), 256, HSMEM>>>(Gf, Wf3, b3, nullptr, embp);
    // pool + head
    gate_kernel<<<BATCH, 512, gate_smem>>>(embp, gw1, gb1, gw2, gb2, comb);
    head_kernel<<<BATCH, 128>>>(comb, rw1, rb1, rw2, rb2, rw3, rb3, out);
}

// round 16
// speedup vs baseline: 1.0177x; 1.0177x over previous
#include <cuda_runtime.h>
#include <cuda_fp16.h>
#include <math.h>
#include <stdint.h>

#define BATCH 512
#define NTOT  65536
typedef unsigned long long u64;
typedef unsigned int u32;

// ---------------- scratch (device globals) ----------------
__device__ __half g_Gf[(size_t)NTOT * 1536];
__device__ __half g_Wf[512 * 640 + 512 * 1536 + 256 * 1536];
__device__ float g_x1[(size_t)512 * NTOT];   // unshifted, channel-major [h][n]
__device__ float g_x2[(size_t)512 * NTOT];
__device__ float g_emb[(size_t)256 * NTOT];
__device__ float g_stats[4 * BATCH];

__device__ __forceinline__ void cpa16(u32 s, const void* g) {
    asm volatile("cp.async.cg.shared.global [%0], [%1], 16;" :: "r"(s), "l"(g));
}
#define CPA_COMMIT() asm volatile("cp.async.commit_group;")
template<int N> __device__ __forceinline__ void cpa_wait() {
    asm volatile("cp.async.wait_group %0;" :: "n"(N));
}
__device__ __forceinline__ void ldsm4(u32* r, u32 addr) {
    asm volatile("ldmatrix.sync.aligned.m8n8.x4.shared.b16 {%0,%1,%2,%3}, [%4];"
        : "=r"(r[0]), "=r"(r[1]), "=r"(r[2]), "=r"(r[3]) : "r"(addr));
}
__device__ __forceinline__ void mma16816(float* c, const u32* a, const u32* b) {
    asm volatile("mma.sync.aligned.m16n8k16.row.col.f32.f16.f16.f32 "
        "{%0,%1,%2,%3}, {%4,%5,%6,%7}, {%8,%9}, {%0,%1,%2,%3};"
        : "+f"(c[0]), "+f"(c[1]), "+f"(c[2]), "+f"(c[3])
        : "r"(a[0]), "r"(a[1]), "r"(a[2]), "r"(a[3]), "r"(b[0]), "r"(b[1]));
}

// ---------------- W convert + K-pad (all three layers, one launch) -----------
#define WS1 (512 * 640)
#define WS2 (512 * 1536)
#define WS3 (256 * 1536)
__global__ __launch_bounds__(256)
void wsplit_all_kernel(const float* __restrict__ w1, const float* __restrict__ w2,
                       const float* __restrict__ w3, __half* __restrict__ wf1,
                       __half* __restrict__ wf2, __half* __restrict__ wf3)
{
    int e = blockIdx.x * 256 + threadIdx.x;
    if (e < WS1) {                          // layer1: K=600 padded to 640
        int h = e / 640, k = e - h * 640;
        float v = (k < 600) ? w1[h * 600 + k] : 0.f;
        wf1[e] = __float2half_rn(v);
        return;
    }
    e -= WS1;
    if (e < WS2) { wf2[e] = __float2half_rn(w2[e]); return; }   // K==KPAD
    e -= WS2;
    if (e < WS3) { wf3[e] = __float2half_rn(w3[e]); }           // K==KPAD
}

// ---------------- gather v8: v6 select chains + 2-row ILP ----------
// G[b*128+j][kbase+k] = T(x at idx). Coalesced u32 stores (lane -> kp).
// MODE 0: in = trees [B][CIN][128], direct idx.
// MODE 1: in = x [CIN][NTOT] unshifted; idx==0 -> sentinel slot 128 (= relu(-mean*inv)),
//         else normed x[idx-1].
#define XPAD 132
template<int CCH, int KPAD, int MODE>
__global__ __launch_bounds__(256)
void gather_kernel(const float* __restrict__ in, const int* __restrict__ idxg,
                   const float* __restrict__ stats_in,
                   __half* __restrict__ Gf, int CIN)
{
    const int b = blockIdx.y, blk = blockIdx.x, tid = threadIdx.x;
    const int c0 = blk * CCH;
    const int kbase = 3 * c0;
    const int klen = (KPAD - kbase < 3 * CCH) ? (KPAD - kbase) : (3 * CCH);
    __shared__ int   idx_s[384];
    __shared__ float x_s[CCH * XPAD];

    float mean = 0.f, inv = 1.f, v0 = 0.f;
    if (MODE == 1) {
        float s  = stats_in[2 * b];
        float s2 = stats_in[2 * b + 1];
        const float N = 65536.f;
        float m   = s / N;
        float var = (s2 - s * s / N) * (1.f / 65535.f);
        mean = m;
        inv  = 1.f / (sqrtf(fmaxf(var, 0.f)) + 1e-5f);
        v0   = fmaxf(-mean * inv, 0.f);
    }
    for (int i = tid; i < 384; i += 256) {
        int v = (i < 381) ? idxg[b * 381 + i] : 0;
        idx_s[i] = (MODE == 1) ? (v ? v - 1 : 128) : v;
    }
    for (int q = tid; q < CCH * 32; q += 256) {
        int cl = q >> 5, vq = q & 31;
        float4 v = make_float4(0.f, 0.f, 0.f, 0.f);
        if (c0 + cl < CIN) {
            const float* src = (MODE == 0)
                ? in + ((size_t)b * CIN + c0 + cl) * 128 + vq * 4
                : in + (size_t)(c0 + cl) * NTOT + b * 128 + vq * 4;
            v = *(const float4*)src;
            if (MODE == 1) {
                v.x = fmaxf((v.x - mean) * inv, 0.f);
                v.y = fmaxf((v.y - mean) * inv, 0.f);
                v.z = fmaxf((v.z - mean) * inv, 0.f);
                v.w = fmaxf((v.w - mean) * inv, 0.f);
            }
        }
        *(float4*)&x_s[cl * XPAD + vq * 4] = v;
    }
    if (MODE == 1) {
        for (int cl = tid; cl < CCH; cl += 256) x_s[cl * XPAD + 128] = v0;
    }
    __syncthreads();

    const int wid = tid >> 5, lane = tid & 31;

    // per-lane invariant element descriptors
    const int NIT = (3 * CCH + 63) / 64;
    int offA[3], rA[3], offB[3], rB[3];
    int nit = 0;
    #pragma unroll
    for (int it = 0; it < NIT && it < 3; it++) {
        int kp = lane + 32 * it;
        if (2 * kp < klen) {
            int e0 = 2 * kp, e1 = e0 + 1;
            int cl0 = e0 / 3, cl1 = e1 / 3;
            offA[it] = cl0 * XPAD; rA[it] = e0 - 3 * cl0;
            offB[it] = cl1 * XPAD; rB[it] = e1 - 3 * cl1;
            nit = it + 1;
        }
    }

    // two independent rows (j, j+8) per iteration for ILP; j+8==127 masked to 0.
    for (int j = wid; j < 128; j += 16) {
        const int jB = j + 8;
        const size_t wbA = ((size_t)(b * 128 + j)  * KPAD + kbase) >> 1;
        const size_t wbB = ((size_t)(b * 128 + jB) * KPAD + kbase) >> 1;
        const int a0 = idx_s[3 * j],  a1 = idx_s[3 * j + 1],  a2 = idx_s[3 * j + 2];
        const int q0 = idx_s[3 * jB], q1 = idx_s[3 * jB + 1], q2 = idx_s[3 * jB + 2];
        const bool zB = (jB == 127);
        #pragma unroll
        for (int it = 0; it < 3; it++) {
            if (it >= nit) break;
            int iA0 = (rA[it] == 0) ? a0 : ((rA[it] == 1) ? a1 : a2);
            int iA1 = (rB[it] == 0) ? a0 : ((rB[it] == 1) ? a1 : a2);
            int iB0 = (rA[it] == 0) ? q0 : ((rA[it] == 1) ? q1 : q2);
            int iB1 = (rB[it] == 0) ? q0 : ((rB[it] == 1) ? q1 : q2);
            float vA0 = x_s[offA[it] + iA0];
            float vA1 = x_s[offB[it] + iA1];
            float vB0 = x_s[offA[it] + iB0];
            float vB1 = x_s[offB[it] + iB1];
            __half2 hA = __floats2half2_rn(vA0, vA1);
            __half2 hB = __floats2half2_rn(vB0, vB1);
            u32 uA = *(u32*)&hA;
            u32 uB = zB ? 0u : *(u32*)&hB;
            ((u32*)Gf)[wbA + lane + 32 * it] = uA;
            ((u32*)Gf)[wbB + lane + 32 * it] = uB;
        }
    }
}

// ---------------- warp-MMA fp16 GEMM (k-tile 64, single sync per tile) -------
// D[h0..h0+128)[n0..n0+128) = sum_k Wf[h][k]*Gf[n][k]
// 256 thr = 8 warps (2m x 4n); warp tile 64m x 32n; k-tile 64,
// double-buffered cp.async: wait -> sync -> stage(c+1) -> mma.
#define HPITCH 144
#define HPLANE (128 * HPITCH)     // 18432
#define HSTAGE (2 * HPLANE)       // 36864: A plane + B plane
#define HSMEM  (2 * HSTAGE)       // 73728

template<int KPAD, int STATS>
__global__ __launch_bounds__(256)
void hmma_gemm_kernel(const __half* __restrict__ Gf, const __half* __restrict__ Wf,
                      const float* __restrict__ bias, float* __restrict__ stats_out,
                      float* __restrict__ out)
{
    extern __shared__ char dsm[];
    __shared__ float bias_s[128];
    __shared__ float rsum[8], rsq[8];
    const int tid = threadIdx.x, wid = tid >> 5, lid = tid & 31;
    const int wm = wid & 1, wn = wid >> 1;
    const int h0 = blockIdx.x * 128;
    const int n0 = blockIdx.y * 128;       // one batch per CTA
    const u32 sbase = (u32)__cvta_generic_to_shared(dsm);

    if (tid < 128) bias_s[tid] = bias[h0 + tid];

    const __half* pl[2] = { Wf + (size_t)h0 * KPAD, Gf + (size_t)n0 * KPAD };

    float acc[4][4][4];
    #pragma unroll
    for (int mi = 0; mi < 4; mi++)
        #pragma unroll
        for (int ni = 0; ni < 4; ni++)
            #pragma unroll
            for (int r = 0; r < 4; r++) acc[mi][ni][r] = 0.f;

    auto stage = [&](int c, int st) {
        int k0 = c * 64;
        u32 sb = sbase + st * HSTAGE;
        #pragma unroll
        for (int i = 0; i < 8; i++) {
            int q = tid + i * 256;                  // 0..2047
            int plane = q >> 10, rem = q & 1023, row = rem >> 3, kc = rem & 7;
            u32 dst = sb + plane * HPLANE + row * HPITCH + kc * 16;
            cpa16(dst, pl[plane] + (size_t)row * KPAD + k0 + kc * 8);
        }
        CPA_COMMIT();
    };

    constexpr int NC = KPAD / 64;
    stage(0, 0);
    for (int c = 0; c < NC; c++) {
        int st = c & 1;
        cpa_wait<0>();
        __syncthreads();
        if (c + 1 < NC) stage(c + 1, st ^ 1);
        u32 sw0 = sbase + st * HSTAGE;
        #pragma unroll
        for (int s2 = 0; s2 < 4; s2++) {
            u32 ah[4][4], bh2[4][2];
            int gAr = ((lid >> 3) & 1) * 8 + (lid & 7);
            int gAb = (lid >> 4) * 16 + s2 * 32;
            #pragma unroll
            for (int mi = 0; mi < 4; mi++) {
                int row = wm * 64 + mi * 16 + gAr;
                ldsm4(ah[mi], sw0 + row * HPITCH + gAb);
            }
            int gBr = (lid >> 4) * 8 + (lid & 7);
            int gBb = ((lid >> 3) & 1) * 16 + s2 * 32;
            #pragma unroll
            for (int t = 0; t < 2; t++) {
                int row = wn * 32 + t * 16 + gBr;
                u32 r4[4];
                ldsm4(r4, sw0 + HPLANE + row * HPITCH + gBb);
                bh2[2 * t][0] = r4[0]; bh2[2 * t][1] = r4[1];
                bh2[2 * t + 1][0] = r4[2]; bh2[2 * t + 1][1] = r4[3];
            }
            #pragma unroll
            for (int mi = 0; mi < 4; mi++)
                #pragma unroll
                for (int ni = 0; ni < 4; ni++) mma16816(acc[mi][ni], ah[mi], bh2[ni]);
        }
    }

    // epilogue: bias + col127->0 + stats + float2 stores
    float lsum = 0.f, lsq = 0.f;
    #pragma unroll
    for (int mi = 0; mi < 4; mi++) {
        #pragma unroll
        for (int ni = 0; ni < 4; ni++) {
            float* cf = acc[mi][ni];
            int hb = h0 + wm * 64 + mi * 16 + (lid >> 2);
            int nb = n0 + wn * 32 + ni * 8 + (lid & 3) * 2;
            int j0 = nb & 127;
            #pragma unroll
            for (int half = 0; half < 2; half++) {
                int h = hb + half * 8;
                float bb = bias_s[h - h0];
                float v0 = cf[half * 2 + 0] + bb;
                float v1 = (j0 == 126) ? 0.f : cf[half * 2 + 1] + bb;
                if (STATS) { lsum += v0 + v1; lsq += v0 * v0 + v1 * v1; }
                float2 stv = make_float2(v0, v1);
                *(float2*)(out + (size_t)h * NTOT + nb) = stv;
            }
        }
    }
    if (STATS) {
        #pragma unroll
        for (int o = 16; o > 0; o >>= 1) {
            lsum += __shfl_xor_sync(0xffffffffu, lsum, o);
            lsq  += __shfl_xor_sync(0xffffffffu, lsq,  o);
        }
        if (lid == 0) { rsum[wid] = lsum; rsq[wid] = lsq; }
        __syncthreads();
        if (tid == 0) {
            float a = 0.f, c2 = 0.f;
            #pragma unroll
            for (int i = 0; i < 8; i++) { a += rsum[i]; c2 += rsq[i]; }
            atomicAdd(&stats_out[2 * blockIdx.y],     a);
            atomicAdd(&stats_out[2 * blockIdx.y + 1], c2);
        }
    }
}

// ---------------- fp32x2 helpers (gate kernel) ----------------
__device__ __forceinline__ u64 fma2(u64 a, u64 b, u64 c) {
    u64 d;
    asm("fma.rn.f32x2 %0, %1, %2, %3;" : "=l"(d) : "l"(a), "l"(b), "l"(c));
    return d;
}
__device__ __forceinline__ u64 rep2(float x) {
    u64 d;
    asm("mov.b64 %0, {%1, %1};" : "=l"(d) : "f"(x));
    return d;
}
__device__ __forceinline__ float2 unpk(u64 a) {
    float2 r;
    asm("mov.b64 {%0, %1}, %2;" : "=f"(r.x), "=f"(r.y) : "l"(a));
    return r;
}

// ---------------- gate + softmax + pool + combined (emb [f][NTOT] unshifted) --
#define GATE_SMEM_FLOATS (256 * 132 + 32 * 130 + 16 * 128 + 128 + 8)
__global__ __launch_bounds__(512, 1)
void gate_kernel(const float* __restrict__ emb, const float* __restrict__ gw1,
                 const float* __restrict__ gb1, const float* __restrict__ gw2,
                 const float* __restrict__ gb2, float* __restrict__ comb)
{
    extern __shared__ float sm[];
    float* et     = sm;
    float* wc     = et + 256 * 132;
    float* red    = wc + 32 * 130;
    float* logits = red + 16 * 128;
    float* rtmp   = logits + 128;

    int b = blockIdx.x, tid = threadIdx.x;
    int tx = tid & 31, ty = tid >> 5;
    const float* eb = emb + (size_t)b * 128;

    for (int q = tid; q < 256 * 32; q += 512) {
        int f = q >> 5, nq = q & 31;
        float4 v = *(const float4*)(eb + (size_t)f * NTOT + nq * 4);
        float* d = &et[f * 132 + nq * 4 + 1];
        d[0] = v.x; d[1] = v.y; d[2] = v.z; d[3] = v.w;
        if (nq == 0) et[f * 132] = 0.f;
    }

    u64 acc[4][4];
    const u64* gb1p = (const u64*)gb1;
    #pragma unroll
    for (int p = 0; p < 4; p++) {
        u64 bp = gb1p[ty * 4 + p];
        #pragma unroll
        for (int u = 0; u < 4; u++) acc[p][u] = bp;
    }
    __syncthreads();

    for (int fc = 0; fc < 256; fc += 32) {
        for (int q = tid; q < 1024; q += 512) {
            int h = q >> 3, flq = q & 7;
            float4 v = *(const float4*)(gw1 + h * 256 + fc + flq * 4);
            wc[(flq * 4 + 0) * 130 + h] = v.x;
            wc[(flq * 4 + 1) * 130 + h] = v.y;
            wc[(flq * 4 + 2) * 130 + h] = v.z;
            wc[(flq * 4 + 3) * 130 + h] = v.w;
        }
        __syncthreads();
        #pragma unroll 4
        for (int fl = 0; fl < 32; fl++) {
            const u64* wp = (const u64*)&wc[fl * 130 + ty * 8];
            u64 wv[4] = {wp[0], wp[1], wp[2], wp[3]};
            float4 g4 = *(const float4*)&et[(fc + fl) * 132 + tx * 4];
            u64 gp0 = rep2(g4.x), gp1 = rep2(g4.y), gp2 = rep2(g4.z), gp3 = rep2(g4.w);
            #pragma unroll
            for (int p = 0; p < 4; p++) {
                acc[p][0] = fma2(wv[p], gp0, acc[p][0]);
                acc[p][1] = fma2(wv[p], gp1, acc[p][1]);
                acc[p][2] = fma2(wv[p], gp2, acc[p][2]);
                acc[p][3] = fma2(wv[p], gp3, acc[p][3]);
            }
        }
        __syncthreads();
    }

    const u64* gw2p = (const u64*)gw2;
    float part[4] = {0.f, 0.f, 0.f, 0.f};
    #pragma unroll
    for (int p = 0; p < 4; p++) {
        float2 wv = unpk(gw2p[ty * 4 + p]);
        #pragma unroll
        for (int u = 0; u < 4; u++) {
            float2 v = unpk(acc[p][u]);
            part[u] += fmaxf(v.x, 0.f) * wv.x + fmaxf(v.y, 0.f) * wv.y;
        }
    }
    #pragma unroll
    for (int u = 0; u < 4; u++) red[ty * 128 + tx * 4 + u] = part[u];
    __syncthreads();

    if (tid < 128) {
        float s = gb2[0];
        #pragma unroll
        for (int t = 0; t < 16; t++) s += red[t * 128 + tid];
        logits[tid] = s;
    }
    __syncthreads();
    if (tid < 128) {
        float v = logits[tid];
        for (int o = 16; o > 0; o >>= 1) v = fmaxf(v, __shfl_xor_sync(0xffffffffu, v, o));
        if ((tid & 31) == 0) rtmp[tid >> 5] = v;
    }
    __syncthreads();
    float gmax = fmaxf(fmaxf(rtmp[0], rtmp[1]), fmaxf(rtmp[2], rtmp[3]));
    if (tid < 128) logits[tid] = expf(logits[tid] - gmax);
    __syncthreads();
    if (tid < 128) {
        float v = logits[tid];
        for (int o = 16; o > 0; o >>= 1) v += __shfl_xor_sync(0xffffffffu, v, o);
        if ((tid & 31) == 0) rtmp[4 + (tid >> 5)] = v;
    }
    __syncthreads();
    float rinv = 1.f / (rtmp[4] + rtmp[5] + rtmp[6] + rtmp[7]);
    if (tid < 128) logits[tid] *= rinv;
    __syncthreads();

    if (tid < 256) {
        int f = tid;
        float pv = 0.f;
        #pragma unroll 8
        for (int n = 0; n < 128; n++) pv += logits[n] * et[f * 132 + n];
        comb[(size_t)b * 512 + f]       = et[f * 132 + 1];
        comb[(size_t)b * 512 + 256 + f] = pv;
    }
}

// ---------------- tiny MLP head ----------------
__global__ __launch_bounds__(128)
void head_kernel(const float* __restrict__ comb,
                 const float* __restrict__ rw1, const float* __restrict__ rb1,
                 const float* __restrict__ rw2, const float* __restrict__ rb2,
                 const float* __restrict__ rw3, const float* __restrict__ rb3,
                 float* __restrict__ outv)
{
    __shared__ float cs[512];
    __shared__ float wcs[128][33];
    __shared__ float h1[128];
    __shared__ float h2[64];
    int b = blockIdx.x, tid = threadIdx.x;

    for (int i = tid; i < 512; i += 128) cs[i] = comb[(size_t)b * 512 + i];

    float a = rb1[tid];
    for (int i0 = 0; i0 < 512; i0 += 32) {
        for (int e = tid; e < 128 * 32; e += 128) {
            int h = e >> 5, il = e & 31;
            wcs[h][il] = rw1[h * 512 + i0 + il];
        }
        __syncthreads();
        #pragma unroll
        for (int il = 0; il < 32; il++) a += cs[i0 + il] * wcs[tid][il];
        __syncthreads();
    }
    h1[tid] = fmaxf(a, 0.f);
    __syncthreads();

    float a2 = (tid < 64) ? rb2[tid] : 0.f;
    for (int i0 = 0; i0 < 128; i0 += 32) {
        for (int e = tid; e < 64 * 32; e += 128) {
            int h = e >> 5, il = e & 31;
            wcs[h][il] = rw2[h * 128 + i0 + il];
        }
        __syncthreads();
        if (tid < 64) {
            #pragma unroll
            for (int il = 0; il < 32; il++) a2 += h1[i0 + il] * wcs[tid][il];
        }
        __syncthreads();
    }
    if (tid < 64) h2[tid] = fmaxf(a2, 0.f);
    __syncthreads();

    if (tid < 64) {
        float p = h2[tid] * rw3[tid];
        for (int o = 16; o > 0; o >>= 1) p += __shfl_xor_sync(0xffffffffu, p, o);
        if ((tid & 31) == 0) h1[64 + (tid >> 5)] = p;
    }
    __syncthreads();
    if (tid == 0) outv[b] = h1[64] + h1[65] + rb3[0];
}

// ---------------- launch ----------------
extern "C" void kernel_launch(void* const* d_in, const int* in_sizes, int n_in,
                              void* d_out, int out_size)
{
    const float* trees = (const float*)d_in[0];
    const int*   idx   = (const int*)  d_in[1];
    const float* w1    = (const float*)d_in[2];
    const float* b1    = (const float*)d_in[3];
    const float* w2    = (const float*)d_in[4];
    const float* b2    = (const float*)d_in[5];
    const float* w3    = (const float*)d_in[6];
    const float* b3    = (const float*)d_in[7];
    const float* gw1   = (const float*)d_in[8];
    const float* gb1   = (const float*)d_in[9];
    const float* gw2   = (const float*)d_in[10];
    const float* gb2   = (const float*)d_in[11];
    const float* rw1   = (const float*)d_in[12];
    const float* rb1   = (const float*)d_in[13];
    const float* rw2   = (const float*)d_in[14];
    const float* rb2   = (const float*)d_in[15];
    const float* rw3   = (const float*)d_in[16];
    const float* rb3   = (const float*)d_in[17];

    float* out  = (float*)d_out;
    float* comb = out + 512;

    float *x1, *x2, *embp, *st;
    __half *Gf, *Wf;
    cudaGetSymbolAddress((void**)&x1,   g_x1);
    cudaGetSymbolAddress((void**)&x2,   g_x2);
    cudaGetSymbolAddress((void**)&embp, g_emb);
    cudaGetSymbolAddress((void**)&Gf,   g_Gf);
    cudaGetSymbolAddress((void**)&Wf,   g_Wf);
    cudaGetSymbolAddress((void**)&st,   g_stats);
    __half* Wf1 = Wf;
    __half* Wf2 = Wf + WS1;
    __half* Wf3 = Wf2 + WS2;
    float* st1 = st;
    float* st2 = st + 2 * BATCH;

    cudaFuncSetAttribute(hmma_gemm_kernel<640, 1>,  cudaFuncAttributeMaxDynamicSharedMemorySize, HSMEM);
    cudaFuncSetAttribute(hmma_gemm_kernel<1536, 1>, cudaFuncAttributeMaxDynamicSharedMemorySize, HSMEM);
    cudaFuncSetAttribute(hmma_gemm_kernel<1536, 0>, cudaFuncAttributeMaxDynamicSharedMemorySize, HSMEM);
    size_t gate_smem = (size_t)GATE_SMEM_FLOATS * sizeof(float);
    cudaFuncSetAttribute(gate_kernel, cudaFuncAttributeMaxDynamicSharedMemorySize, (int)gate_smem);

    cudaMemsetAsync(st, 0, 4 * BATCH * sizeof(float));

    wsplit_all_kernel<<<(WS1 + WS2 + WS3 + 255) / 256, 256>>>(w1, w2, w3, Wf1, Wf2, Wf3);

    // layer 1
    gather_kernel<40, 640, 0><<<dim3(6, BATCH), 256>>>(trees, idx, nullptr, Gf, 200);
    hmma_gemm_kernel<640, 1><<<dim3(4, BATCH), 256, HSMEM>>>(Gf, Wf1, b1, st1, x1);
    // layer 2
    gather_kernel<64, 1536, 1><<<dim3(8, BATCH), 256>>>(x1, idx, st1, Gf, 512);
    hmma_gemm_kernel<1536, 1><<<dim3(4, BATCH), 256, HSMEM>>>(Gf, Wf2, b2, st2, x2);
    // layer 3
    gather_kernel<64, 1536, 1><<<dim3(8, BATCH), 256>>>(x2, idx, st2, Gf, 512);
    hmma_gemm_kernel<1536, 0><<<dim3(2, BATCH), 256, HSMEM>>>(Gf, Wf3, b3, nullptr, embp);
    // pool + head
    gate_kernel<<<BATCH, 512, gate_smem>>>(embp, gw1, gb1, gw2, gb2, comb);
    head_kernel<<<BATCH, 128>>>(comb, rw1, rb1, rw2, rb2, rw3, rb3, out);
}